// round 14
// baseline (speedup 1.0000x reference)
#include <cuda_runtime.h>
#include <cuda_bf16.h>
#include <cstdint>

// DCNv2 R14: prep kernels (x transpose to NHWC + W bf16 hi/lo pre-split)
// feeding the fused gather + mma.sync m16n8k16 hi/lo GEMM from R13.
// CTA: M=128 outputs x N=128 pixels, grid=256, 512 threads, 4x4 warps m32n32.
// 72-k chunks (8 ch x 9 taps), k padded to 80, 3 MMA passes ~ fp32 accuracy.

#define NTHREADS 512
#define NCHUNK 16
#define LDT 88                       // W tile row length (bf16), 176B rows

#define T_WHI 0
#define T_WLO 22528
#define T_SHI 45056
#define T_SLO 65536
#define BUF_BYTES 86016
#define SMEM_BYTES (2 * BUF_BYTES)   // 172032

__device__ float g_xT[8 * 4096 * 128];     // x transposed to [b][y*64+x][c]
__device__ uint2 g_wsp[16 * 4608];         // per chunk: 2304 hi uint2, 2304 lo

#define MMA_BF16(d, a, b)                                                     \
    asm volatile(                                                             \
        "mma.sync.aligned.m16n8k16.row.col.f32.bf16.bf16.f32 "                \
        "{%0,%1,%2,%3}, {%4,%5,%6,%7}, {%8,%9}, {%0,%1,%2,%3};"               \
        : "+f"((d)[0]), "+f"((d)[1]), "+f"((d)[2]), "+f"((d)[3])              \
        : "r"((a)[0]), "r"((a)[1]), "r"((a)[2]), "r"((a)[3]),                 \
          "r"((b)[0]), "r"((b)[1]))

#define LDSM_X4(r, addr)                                                      \
    asm volatile("ldmatrix.sync.aligned.m8n8.x4.shared.b16 {%0,%1,%2,%3}, [%4];" \
                 : "=r"((r)[0]), "=r"((r)[1]), "=r"((r)[2]), "=r"((r)[3])     \
                 : "r"(addr))

#define LDSM_X4T(r, addr)                                                     \
    asm volatile("ldmatrix.sync.aligned.m8n8.x4.trans.shared.b16 {%0,%1,%2,%3}, [%4];" \
                 : "=r"((r)[0]), "=r"((r)[1]), "=r"((r)[2]), "=r"((r)[3])     \
                 : "r"(addr))

__device__ __forceinline__ uint32_t smem_u32(const void* p) {
    uint32_t a;
    asm("{ .reg .u64 t; cvta.to.shared.u64 t, %1; cvt.u32.u64 %0, t; }" : "=r"(a) : "l"(p));
    return a;
}

// ---- prep 1: transpose x [B,C,H,W] -> g_xT [B, H*W, C] -------------------
__global__ void __launch_bounds__(256)
xpose_kernel(const float* __restrict__ x) {
    __shared__ float tile[128 * 65];
    const int b = blockIdx.x >> 6;
    const int y = blockIdx.x & 63;
    const float* src = x + ((size_t)b << 19) + (y << 6);
#pragma unroll
    for (int i = threadIdx.x; i < 8192; i += 256) {
        const int c = i >> 6, xx = i & 63;
        tile[c * 65 + xx] = src[(c << 12) + xx];
    }
    __syncthreads();
    float* dst = g_xT + ((size_t)b << 19) + ((size_t)(y << 6) << 7);
#pragma unroll
    for (int i = threadIdx.x; i < 8192; i += 256) {
        const int xx = i >> 7, c = i & 127;
        dst[(xx << 7) + c] = tile[c * 65 + xx];
    }
}

// ---- prep 2: split W into bf16 hi/lo, chunk-major ------------------------
__global__ void __launch_bounds__(512)
wprep_kernel(const float* __restrict__ weight) {
    const int ch = blockIdx.x;
    for (int i = threadIdx.x; i < 2304; i += 512) {
        const int o = i / 18, kq = i - o * 18;
        const float4 f = *(const float4*)(weight + (size_t)o * 1152 + ch * 72 + kq * 4);
        __nv_bfloat162 h01 = __floats2bfloat162_rn(f.x, f.y);
        __nv_bfloat162 h23 = __floats2bfloat162_rn(f.z, f.w);
        const float2 g01 = __bfloat1622float2(h01);
        const float2 g23 = __bfloat1622float2(h23);
        __nv_bfloat162 l01 = __floats2bfloat162_rn(f.x - g01.x, f.y - g01.y);
        __nv_bfloat162 l23 = __floats2bfloat162_rn(f.z - g23.x, f.w - g23.y);
        g_wsp[ch * 4608 + i]        = make_uint2(*(uint32_t*)&h01, *(uint32_t*)&h23);
        g_wsp[ch * 4608 + 2304 + i] = make_uint2(*(uint32_t*)&l01, *(uint32_t*)&l23);
    }
}

__global__ void __launch_bounds__(NTHREADS, 1)
dcn_v2_kernel(const float* __restrict__ offsets,
              const float* __restrict__ mask,
              const float* __restrict__ bias,
              float* __restrict__ out) {
    extern __shared__ char smem[];
    const uint32_t sb = smem_u32(smem);

    const int tid  = threadIdx.x;
    const int wid  = tid >> 5;
    const int lane = tid & 31;
    const int grp  = lane >> 2;
    const int qp   = lane & 3;
    const int wm   = wid >> 2;
    const int wn   = wid & 3;

    const int bIdx = blockIdx.x >> 5;
    const int h0   = (blockIdx.x & 31) << 1;
    const float* xTb = g_xT + ((size_t)bIdx << 19);

    // ---- one-time zero of padded tail rows --------------------------------
#pragma unroll
    for (int r = 0; r < 2; ++r) {
        char* bb = smem + r * BUF_BYTES;
        ((uint32_t*)(bb + T_SHI + 72 * 256))[tid] = 0;
        ((uint32_t*)(bb + T_SLO + 72 * 256))[tid] = 0;
#pragma unroll
        for (int i = tid; i < 1024; i += NTHREADS) {
            const int o = i >> 3, w = i & 7;
            const int off = o * 176 + 144 + w * 4;
            *(uint32_t*)(bb + T_WHI + off) = 0;
            *(uint32_t*)(bb + T_WLO + off) = 0;
        }
    }

    // ---- register-resident bilinear taps ----------------------------------
    const int ntaps = 2 + (tid < 128);
    uint2  tio[3];
    float4 twt[3];
#pragma unroll
    for (int j = 0; j < 3; ++j) {
        tio[j] = make_uint2(0u, 0u);
        twt[j] = make_float4(0.f, 0.f, 0.f, 0.f);
        if (j < ntaps) {
            const int e   = tid + (j << 9);
            const int t   = e >> 7;
            const int pix = e & 127;
            const int h   = h0 + (pix >> 6);
            const int wp  = pix & 63;
            const int ky  = t / 3;
            const int kx  = t - ky * 3;
            const int hw  = (h << 6) + wp;

            const size_t ob = ((size_t)bIdx * 18) << 12;
            const float dy = offsets[ob + ((size_t)(2 * t) << 12) + hw];
            const float dx = offsets[ob + ((size_t)(2 * t + 1) << 12) + hw];
            const float m  = mask[(((size_t)bIdx * 9 + t) << 12) + hw];

            const float py = (float)(h - 1 + ky) + dy;
            const float px = (float)(wp - 1 + kx) + dx;
            const float fy = floorf(py), fx = floorf(px);
            const float ay = py - fy, ax = px - fx;
            const float by = 1.f - ay, bx = 1.f - ax;
            const float fy1 = fy + 1.f, fx1 = fx + 1.f;
            const bool vy0 = (fy  >= 0.f) && (fy  <= 63.f);
            const bool vy1 = (fy1 >= 0.f) && (fy1 <= 63.f);
            const bool vx0 = (fx  >= 0.f) && (fx  <= 63.f);
            const bool vx1 = (fx1 >= 0.f) && (fx1 <= 63.f);
            const int y0 = (int)fminf(fmaxf(fy,  0.f), 63.f);
            const int y1 = (int)fminf(fmaxf(fy1, 0.f), 63.f);
            const int x0 = (int)fminf(fmaxf(fx,  0.f), 63.f);
            const int x1 = (int)fminf(fmaxf(fx1, 0.f), 63.f);
            const unsigned i0 = (unsigned)((y0 << 6) + x0);
            const unsigned i1 = (unsigned)((y0 << 6) + x1);
            const unsigned i2 = (unsigned)((y1 << 6) + x0);
            const unsigned i3 = (unsigned)((y1 << 6) + x1);
            tio[j] = make_uint2(i0 | (i1 << 16), i2 | (i3 << 16));
            twt[j] = make_float4((vy0 && vx0) ? by * bx * m : 0.f,
                                 (vy0 && vx1) ? by * ax * m : 0.f,
                                 (vy1 && vx0) ? ay * bx * m : 0.f,
                                 (vy1 && vx1) ? ay * ax * m : 0.f);
        }
    }

    float acc[2][4][4];
#pragma unroll
    for (int mi = 0; mi < 2; ++mi)
#pragma unroll
        for (int ni = 0; ni < 4; ++ni)
#pragma unroll
            for (int q = 0; q < 4; ++q) acc[mi][ni][q] = 0.f;

    // ---- staging helpers ---------------------------------------------------
    // gather 4 channels per owned tap from NHWC layout: one LDG.128 per corner
#define GATHER_HALF(V, CB, U0)                                                \
    do {                                                                      \
        const float* qc = xTb + (CB) + (U0);                                  \
        _Pragma("unroll")                                                     \
        for (int j = 0; j < 3; ++j) {                                         \
            if (j < ntaps) {                                                  \
                const float4 w = twt[j];                                      \
                const float4 f0 = __ldg((const float4*)(qc + ((tio[j].x & 0xFFFF) << 7))); \
                const float4 f1 = __ldg((const float4*)(qc + ((tio[j].x >> 16) << 7)));    \
                const float4 f2 = __ldg((const float4*)(qc + ((tio[j].y & 0xFFFF) << 7))); \
                const float4 f3 = __ldg((const float4*)(qc + ((tio[j].y >> 16) << 7)));    \
                V[j][0] = fmaf(w.x, f0.x, fmaf(w.y, f1.x, fmaf(w.z, f2.x, w.w * f3.x))); \
                V[j][1] = fmaf(w.x, f0.y, fmaf(w.y, f1.y, fmaf(w.z, f2.y, w.w * f3.y))); \
                V[j][2] = fmaf(w.x, f0.z, fmaf(w.y, f1.z, fmaf(w.z, f2.z, w.w * f3.z))); \
                V[j][3] = fmaf(w.x, f0.w, fmaf(w.y, f1.w, fmaf(w.z, f2.w, w.w * f3.w))); \
            }                                                                 \
        }                                                                     \
    } while (0)

#define COMMIT_HALF(V, BUFB_HOST, U0)                                         \
    do {                                                                      \
        char* shi = smem + (BUFB_HOST) + T_SHI;                               \
        char* slo = smem + (BUFB_HOST) + T_SLO;                               \
        _Pragma("unroll")                                                     \
        for (int j = 0; j < 3; ++j) {                                         \
            if (j < ntaps) {                                                  \
                const int e    = tid + (j << 9);                              \
                const int t    = e >> 7;                                      \
                const int pix2 = (e & 127) * 2;                               \
                const int tb   = t << 8;                                      \
                const int t4   = t << 4;                                      \
                _Pragma("unroll")                                             \
                for (int u = 0; u < 4; ++u) {                                 \
                    const int c = (U0) + u;                                   \
                    const float v = V[j][u];                                  \
                    const __nv_bfloat16 hb = __float2bfloat16(v);             \
                    const __nv_bfloat16 lb =                                  \
                        __float2bfloat16(v - __bfloat162float(hb));           \
                    const int ad = tb + c * 2304 +                            \
                                   (pix2 ^ ((t4 + (c << 4)) & 0x70));         \
                    *(__nv_bfloat16*)(shi + ad) = hb;                         \
                    *(__nv_bfloat16*)(slo + ad) = lb;                         \
                }                                                             \
            }                                                                 \
        }                                                                     \
    } while (0)

    // W stage: pre-split uint2 copy. 4608 uint2 per chunk (hi 0..2303, lo rest)
#define W_LOAD_A(WF, CH)                                                      \
    do {                                                                      \
        const uint2* ws = g_wsp + (CH) * 4608;                                \
        _Pragma("unroll")                                                     \
        for (int it = 0; it < 4; ++it)                                        \
            WF[it] = __ldg(ws + tid + it * NTHREADS);                         \
    } while (0)

#define W_LOAD_B(WF, CH)                                                      \
    do {                                                                      \
        const uint2* ws = g_wsp + (CH) * 4608;                                \
        _Pragma("unroll")                                                     \
        for (int it = 4; it < 9; ++it)                                        \
            WF[it - 4] = __ldg(ws + tid + it * NTHREADS);                     \
    } while (0)

#define W_COMMIT_ONE(F, IDX, BUFB_HOST)                                       \
    do {                                                                      \
        const int hf = (IDX) >= 2304;                                         \
        const int r  = (IDX) - (hf ? 2304 : 0);                               \
        const int o  = r / 18;                                                \
        const int kq = r - o * 18;                                            \
        char* dst = smem + (BUFB_HOST) + (hf ? T_WLO : T_WHI) + o * 176 + kq * 8; \
        *(uint2*)dst = (F);                                                   \
    } while (0)

#define W_COMMIT_A(WF, BUFB_HOST)                                             \
    do {                                                                      \
        _Pragma("unroll")                                                     \
        for (int it = 0; it < 4; ++it)                                        \
            W_COMMIT_ONE(WF[it], tid + it * NTHREADS, BUFB_HOST);             \
    } while (0)

#define W_COMMIT_B(WF, BUFB_HOST)                                             \
    do {                                                                      \
        _Pragma("unroll")                                                     \
        for (int it = 4; it < 9; ++it)                                        \
            W_COMMIT_ONE(WF[it - 4], tid + it * NTHREADS, BUFB_HOST);         \
    } while (0)

    // ---- MMA lane addressing -----------------------------------------------
    const int lr   = lane >> 3;
    const int lrow = lane & 7;
    const uint32_t a_lane_off =
        (uint32_t)(((wm * 32 + (lr & 1) * 8 + lrow) * LDT + (lr >> 1) * 8) * 2);
    const uint32_t b_lane_const =
        (uint32_t)(((lr & 1) * 8 + lrow) * 256) + (uint32_t)((lr >> 1) ? T_SLO : T_SHI);
    const uint32_t xorv = (uint32_t)(lrow << 4);
    const uint32_t wn64 = (uint32_t)(wn * 64);

#define MMA_PART(BUFB, KS0, KS1)                                              \
    do {                                                                      \
        const uint32_t whiA = (BUFB) + T_WHI + a_lane_off;                    \
        const uint32_t wloA = (BUFB) + T_WLO + a_lane_off;                    \
        const uint32_t bB   = (BUFB) + b_lane_const;                          \
        _Pragma("unroll")                                                     \
        for (int ks = (KS0); ks < (KS1); ++ks) {                              \
            uint32_t ahi[2][4], alo[2][4];                                    \
            _Pragma("unroll")                                                 \
            for (int mi = 0; mi < 2; ++mi) {                                  \
                LDSM_X4(ahi[mi], whiA + (uint32_t)((mi * 16 * LDT + ks * 16) * 2)); \
                LDSM_X4(alo[mi], wloA + (uint32_t)((mi * 16 * LDT + ks * 16) * 2)); \
            }                                                                 \
            _Pragma("unroll")                                                 \
            for (int ni = 0; ni < 4; ++ni) {                                  \
                uint32_t b4[4];                                               \
                LDSM_X4T(b4, bB + (uint32_t)(ks * 4096) +                     \
                              ((wn64 + (uint32_t)(ni * 16)) ^ xorv));         \
                _Pragma("unroll")                                             \
                for (int mi = 0; mi < 2; ++mi) {                              \
                    MMA_BF16(acc[mi][ni], ahi[mi], b4);                       \
                    MMA_BF16(acc[mi][ni], ahi[mi], b4 + 2);                   \
                    MMA_BF16(acc[mi][ni], alo[mi], b4);                       \
                }                                                             \
            }                                                                 \
        }                                                                     \
    } while (0)

    // ---- prologue: fill buffer 0 -------------------------------------------
    {
        float vA[3][4], vB[3][4];
        uint2 wfa[4], wfb[5];
        W_LOAD_A(wfa, 0);
        W_LOAD_B(wfb, 0);
        GATHER_HALF(vA, 0, 0);
        GATHER_HALF(vB, 0, 4);
        W_COMMIT_A(wfa, 0);
        W_COMMIT_B(wfb, 0);
        COMMIT_HALF(vA, 0, 0);
        COMMIT_HALF(vB, 0, 4);
    }
    __syncthreads();

    // ---- main loop -----------------------------------------------------------
    for (int ch = 0; ch < NCHUNK; ++ch) {
        const int cur = ch & 1;
        const uint32_t bufb = sb + (uint32_t)(cur * BUF_BYTES);
        const int nxt = (cur ^ 1) * BUF_BYTES;
        const bool sv = (ch + 1 < NCHUNK);
        const int cb  = (ch + 1) * 8;     // channel base of next chunk

        float vH[3][4];
        uint2 wfa[4], wfb[5];

        if (sv) { W_LOAD_A(wfa, ch + 1); GATHER_HALF(vH, cb, 0); }
        MMA_PART(bufb, 0, 2);
        if (sv) { W_COMMIT_A(wfa, nxt); COMMIT_HALF(vH, nxt, 0); }

        if (sv) { W_LOAD_B(wfb, ch + 1); GATHER_HALF(vH, cb, 4); }
        MMA_PART(bufb, 2, 5);
        if (sv) { W_COMMIT_B(wfb, nxt); COMMIT_HALF(vH, nxt, 4); }

        __syncthreads();
    }

    // ---- epilogue: + bias, float2 stores ------------------------------------
#pragma unroll
    for (int mi = 0; mi < 2; ++mi) {
#pragma unroll
        for (int half = 0; half < 2; ++half) {
            const int o = wm * 32 + mi * 16 + grp + half * 8;
            const float bi = __ldg(bias + o);
            float* po = out + (((size_t)bIdx * 128 + o) << 12) + (h0 << 6);
#pragma unroll
            for (int ni = 0; ni < 4; ++ni) {
                const int n = wn * 32 + ni * 8 + qp * 2;
                float2 v;
                v.x = acc[mi][ni][half * 2 + 0] + bi;
                v.y = acc[mi][ni][half * 2 + 1] + bi;
                *(float2*)(po + n) = v;
            }
        }
    }
}

extern "C" void kernel_launch(void* const* d_in, const int* in_sizes, int n_in,
                              void* d_out, int out_size) {
    const float* x       = (const float*)d_in[0];
    const float* offsets = (const float*)d_in[1];
    const float* mask    = (const float*)d_in[2];
    const float* weight  = (const float*)d_in[3];
    const float* bias    = (const float*)d_in[4];
    float* out = (float*)d_out;

    cudaFuncSetAttribute(dcn_v2_kernel,
                         cudaFuncAttributeMaxDynamicSharedMemorySize, SMEM_BYTES);

    xpose_kernel<<<512, 256>>>(x);
    wprep_kernel<<<16, 512>>>(weight);
    dcn_v2_kernel<<<256, NTHREADS, SMEM_BYTES>>>(offsets, mask, bias, out);
}

// round 15
// speedup vs baseline: 1.6450x; 1.6450x over previous
#include <cuda_runtime.h>
#include <cuda_bf16.h>
#include <cstdint>

// DCNv2 R15: R13 fused gather + mma.sync hi/lo GEMM, with W tiles pre-split
// into padded smem-image form by a prep kernel and staged via cp.async.
// CTA: M=128 outputs x N=128 pixels, grid=256, 512 threads, 4x4 warps m32n32.
// 72-k chunks (8 ch x 9 taps), k padded to 80, 3 MMA passes ~ fp32 accuracy.

#define NTHREADS 512
#define NCHUNK 16
#define LDT 88                       // W tile row length (bf16), 176B rows

#define T_WHI 0
#define T_WLO 22528
#define T_SHI 45056
#define T_SLO 65536
#define BUF_BYTES 86016
#define SMEM_BYTES (2 * BUF_BYTES)   // 172032

#define W_IMG_BYTES 45056            // hi tile (22528) + lo tile (22528)
#define W_CP_CHUNKS (W_IMG_BYTES / 16)   // 2816

__device__ __align__(16) char g_wsp[16 * W_IMG_BYTES];  // per-chunk W tile images

#define MMA_BF16(d, a, b)                                                     \
    asm volatile(                                                             \
        "mma.sync.aligned.m16n8k16.row.col.f32.bf16.bf16.f32 "                \
        "{%0,%1,%2,%3}, {%4,%5,%6,%7}, {%8,%9}, {%0,%1,%2,%3};"               \
        : "+f"((d)[0]), "+f"((d)[1]), "+f"((d)[2]), "+f"((d)[3])              \
        : "r"((a)[0]), "r"((a)[1]), "r"((a)[2]), "r"((a)[3]),                 \
          "r"((b)[0]), "r"((b)[1]))

#define LDSM_X4(r, addr)                                                      \
    asm volatile("ldmatrix.sync.aligned.m8n8.x4.shared.b16 {%0,%1,%2,%3}, [%4];" \
                 : "=r"((r)[0]), "=r"((r)[1]), "=r"((r)[2]), "=r"((r)[3])     \
                 : "r"(addr))

#define LDSM_X4T(r, addr)                                                     \
    asm volatile("ldmatrix.sync.aligned.m8n8.x4.trans.shared.b16 {%0,%1,%2,%3}, [%4];" \
                 : "=r"((r)[0]), "=r"((r)[1]), "=r"((r)[2]), "=r"((r)[3])     \
                 : "r"(addr))

#define CP16(DST, SRC)                                                        \
    asm volatile("cp.async.cg.shared.global [%0], [%1], 16;"                  \
                 :: "r"(DST), "l"(SRC) : "memory")
#define CP_COMMIT() asm volatile("cp.async.commit_group;" ::: "memory")
#define CP_WAIT0()  asm volatile("cp.async.wait_group 0;" ::: "memory")

__device__ __forceinline__ uint32_t smem_u32(const void* p) {
    uint32_t a;
    asm("{ .reg .u64 t; cvta.to.shared.u64 t, %1; cvt.u32.u64 %0, t; }" : "=r"(a) : "l"(p));
    return a;
}

// ---- prep: split W into bf16 hi/lo padded tile images (smem byte layout) --
__global__ void __launch_bounds__(512)
wprep_kernel(const float* __restrict__ weight) {
    const int ch = blockIdx.x;
    char* base = g_wsp + (size_t)ch * W_IMG_BYTES;
    for (int i = threadIdx.x; i < 2304; i += 512) {
        const int o = i / 18, kq = i - o * 18;
        const float4 f = *(const float4*)(weight + (size_t)o * 1152 + ch * 72 + kq * 4);
        __nv_bfloat162 h01 = __floats2bfloat162_rn(f.x, f.y);
        __nv_bfloat162 h23 = __floats2bfloat162_rn(f.z, f.w);
        const float2 g01 = __bfloat1622float2(h01);
        const float2 g23 = __bfloat1622float2(h23);
        __nv_bfloat162 l01 = __floats2bfloat162_rn(f.x - g01.x, f.y - g01.y);
        __nv_bfloat162 l23 = __floats2bfloat162_rn(f.z - g23.x, f.w - g23.y);
        const int bo = o * 176 + kq * 8;
        *(uint2*)(base + bo)         = make_uint2(*(uint32_t*)&h01, *(uint32_t*)&h23);
        *(uint2*)(base + 22528 + bo) = make_uint2(*(uint32_t*)&l01, *(uint32_t*)&l23);
    }
    // zero pad columns 72..87 of every row, both tiles
    for (int i = threadIdx.x; i < 1024; i += 512) {
        const int o = i >> 3, w = i & 7;
        const int off = o * 176 + 144 + w * 4;
        *(uint32_t*)(base + off) = 0;
        *(uint32_t*)(base + 22528 + off) = 0;
    }
}

__global__ void __launch_bounds__(NTHREADS, 1)
dcn_v2_kernel(const float* __restrict__ x,
              const float* __restrict__ offsets,
              const float* __restrict__ mask,
              const float* __restrict__ bias,
              float* __restrict__ out) {
    extern __shared__ char smem[];
    const uint32_t sb = smem_u32(smem);

    const int tid  = threadIdx.x;
    const int wid  = tid >> 5;
    const int lane = tid & 31;
    const int grp  = lane >> 2;
    const int qp   = lane & 3;
    const int wm   = wid >> 2;
    const int wn   = wid & 3;

    const int bIdx = blockIdx.x >> 5;
    const int h0   = (blockIdx.x & 31) << 1;
    const float* xp = x + ((size_t)bIdx << 19);

    // ---- one-time zero of S padded tail rows (k 72..79) -------------------
#pragma unroll
    for (int r = 0; r < 2; ++r) {
        char* bb = smem + r * BUF_BYTES;
        ((uint32_t*)(bb + T_SHI + 72 * 256))[tid] = 0;
        ((uint32_t*)(bb + T_SLO + 72 * 256))[tid] = 0;
    }

    // ---- register-resident bilinear taps ----------------------------------
    const int ntaps = 2 + (tid < 128);
    uint2  tio[3];
    float4 twt[3];
#pragma unroll
    for (int j = 0; j < 3; ++j) {
        tio[j] = make_uint2(0u, 0u);
        twt[j] = make_float4(0.f, 0.f, 0.f, 0.f);
        if (j < ntaps) {
            const int e   = tid + (j << 9);
            const int t   = e >> 7;
            const int pix = e & 127;
            const int h   = h0 + (pix >> 6);
            const int wp  = pix & 63;
            const int ky  = t / 3;
            const int kx  = t - ky * 3;
            const int hw  = (h << 6) + wp;

            const size_t ob = ((size_t)bIdx * 18) << 12;
            const float dy = offsets[ob + ((size_t)(2 * t) << 12) + hw];
            const float dx = offsets[ob + ((size_t)(2 * t + 1) << 12) + hw];
            const float m  = mask[(((size_t)bIdx * 9 + t) << 12) + hw];

            const float py = (float)(h - 1 + ky) + dy;
            const float px = (float)(wp - 1 + kx) + dx;
            const float fy = floorf(py), fx = floorf(px);
            const float ay = py - fy, ax = px - fx;
            const float by = 1.f - ay, bx = 1.f - ax;
            const float fy1 = fy + 1.f, fx1 = fx + 1.f;
            const bool vy0 = (fy  >= 0.f) && (fy  <= 63.f);
            const bool vy1 = (fy1 >= 0.f) && (fy1 <= 63.f);
            const bool vx0 = (fx  >= 0.f) && (fx  <= 63.f);
            const bool vx1 = (fx1 >= 0.f) && (fx1 <= 63.f);
            const int y0 = (int)fminf(fmaxf(fy,  0.f), 63.f);
            const int y1 = (int)fminf(fmaxf(fy1, 0.f), 63.f);
            const int x0 = (int)fminf(fmaxf(fx,  0.f), 63.f);
            const int x1 = (int)fminf(fmaxf(fx1, 0.f), 63.f);
            const unsigned i0 = (unsigned)((y0 << 6) + x0);
            const unsigned i1 = (unsigned)((y0 << 6) + x1);
            const unsigned i2 = (unsigned)((y1 << 6) + x0);
            const unsigned i3 = (unsigned)((y1 << 6) + x1);
            tio[j] = make_uint2(i0 | (i1 << 16), i2 | (i3 << 16));
            twt[j] = make_float4((vy0 && vx0) ? by * bx * m : 0.f,
                                 (vy0 && vx1) ? by * ax * m : 0.f,
                                 (vy1 && vx0) ? ay * bx * m : 0.f,
                                 (vy1 && vx1) ? ay * ax * m : 0.f);
        }
    }

    float acc[2][4][4];
#pragma unroll
    for (int mi = 0; mi < 2; ++mi)
#pragma unroll
        for (int ni = 0; ni < 4; ++ni)
#pragma unroll
            for (int q = 0; q < 4; ++q) acc[mi][ni][q] = 0.f;

    // ---- staging helpers ---------------------------------------------------
#define GATHER_HALF(V, CB, U0)                                                \
    do {                                                                      \
        const float* qc = xp + ((size_t)(CB) << 12);                          \
        _Pragma("unroll")                                                     \
        for (int j = 0; j < 3; ++j) {                                         \
            if (j < ntaps) {                                                  \
                const float4 w = twt[j];                                      \
                const float* b0 = qc + (tio[j].x & 0xFFFF);                   \
                const float* b1 = qc + (tio[j].x >> 16);                      \
                const float* b2 = qc + (tio[j].y & 0xFFFF);                   \
                const float* b3 = qc + (tio[j].y >> 16);                      \
                _Pragma("unroll")                                             \
                for (int u = 0; u < 4; ++u) {                                 \
                    const int co = ((U0) + u) << 12;                          \
                    V[j][u] = fmaf(w.x, __ldg(b0 + co),                       \
                              fmaf(w.y, __ldg(b1 + co),                       \
                              fmaf(w.z, __ldg(b2 + co),                       \
                                   w.w * __ldg(b3 + co))));                   \
                }                                                             \
            }                                                                 \
        }                                                                     \
    } while (0)

#define COMMIT_HALF(V, BUFB_HOST, U0)                                         \
    do {                                                                      \
        char* shi = smem + (BUFB_HOST) + T_SHI;                               \
        char* slo = smem + (BUFB_HOST) + T_SLO;                               \
        _Pragma("unroll")                                                     \
        for (int j = 0; j < 3; ++j) {                                         \
            if (j < ntaps) {                                                  \
                const int e    = tid + (j << 9);                              \
                const int t    = e >> 7;                                      \
                const int pix2 = (e & 127) * 2;                               \
                const int tb   = t << 8;                                      \
                const int t4   = t << 4;                                      \
                _Pragma("unroll")                                             \
                for (int u = 0; u < 4; ++u) {                                 \
                    const int c = (U0) + u;                                   \
                    const float v = V[j][u];                                  \
                    const __nv_bfloat16 hb = __float2bfloat16(v);             \
                    const __nv_bfloat16 lb =                                  \
                        __float2bfloat16(v - __bfloat162float(hb));           \
                    const int ad = tb + c * 2304 +                            \
                                   (pix2 ^ ((t4 + (c << 4)) & 0x70));         \
                    *(__nv_bfloat16*)(shi + ad) = hb;                         \
                    *(__nv_bfloat16*)(slo + ad) = lb;                         \
                }                                                             \
            }                                                                 \
        }                                                                     \
    } while (0)

    // W stage: async flat copy of the pre-built tile image (2816 x 16B)
#define W_CP(BUFB_U32, CH, IT0, IT1)                                          \
    do {                                                                      \
        const char* wsrc = g_wsp + (size_t)(CH) * W_IMG_BYTES;                \
        _Pragma("unroll")                                                     \
        for (int it = (IT0); it < (IT1); ++it) {                              \
            const int idx = tid + it * NTHREADS;                              \
            if (idx < W_CP_CHUNKS)                                            \
                CP16((BUFB_U32) + (uint32_t)(idx * 16), wsrc + idx * 16);     \
        }                                                                     \
        CP_COMMIT();                                                          \
    } while (0)

    // ---- MMA lane addressing -----------------------------------------------
    const int lr   = lane >> 3;
    const int lrow = lane & 7;
    const uint32_t a_lane_off =
        (uint32_t)(((wm * 32 + (lr & 1) * 8 + lrow) * LDT + (lr >> 1) * 8) * 2);
    const uint32_t b_lane_const =
        (uint32_t)(((lr & 1) * 8 + lrow) * 256) + (uint32_t)((lr >> 1) ? T_SLO : T_SHI);
    const uint32_t xorv = (uint32_t)(lrow << 4);
    const uint32_t wn64 = (uint32_t)(wn * 64);

#define MMA_PART(BUFB, KS0, KS1)                                              \
    do {                                                                      \
        const uint32_t whiA = (BUFB) + T_WHI + a_lane_off;                    \
        const uint32_t wloA = (BUFB) + T_WLO + a_lane_off;                    \
        const uint32_t bB   = (BUFB) + b_lane_const;                          \
        _Pragma("unroll")                                                     \
        for (int ks = (KS0); ks < (KS1); ++ks) {                              \
            uint32_t ahi[2][4], alo[2][4];                                    \
            _Pragma("unroll")                                                 \
            for (int mi = 0; mi < 2; ++mi) {                                  \
                LDSM_X4(ahi[mi], whiA + (uint32_t)((mi * 16 * LDT + ks * 16) * 2)); \
                LDSM_X4(alo[mi], wloA + (uint32_t)((mi * 16 * LDT + ks * 16) * 2)); \
            }                                                                 \
            _Pragma("unroll")                                                 \
            for (int ni = 0; ni < 4; ++ni) {                                  \
                uint32_t b4[4];                                               \
                LDSM_X4T(b4, bB + (uint32_t)(ks * 4096) +                     \
                              ((wn64 + (uint32_t)(ni * 16)) ^ xorv));         \
                _Pragma("unroll")                                             \
                for (int mi = 0; mi < 2; ++mi) {                              \
                    MMA_BF16(acc[mi][ni], ahi[mi], b4);                       \
                    MMA_BF16(acc[mi][ni], ahi[mi], b4 + 2);                   \
                    MMA_BF16(acc[mi][ni], alo[mi], b4);                       \
                }                                                             \
            }                                                                 \
        }                                                                     \
    } while (0)

    // ---- prologue: fill buffer 0 -------------------------------------------
    {
        W_CP(sb, 0, 0, 6);
        float vA[3][4], vB[3][4];
        GATHER_HALF(vA, 0, 0);
        GATHER_HALF(vB, 0, 4);
        COMMIT_HALF(vA, 0, 0);
        COMMIT_HALF(vB, 0, 4);
        CP_WAIT0();
    }
    __syncthreads();

    // ---- main loop -----------------------------------------------------------
    for (int ch = 0; ch < NCHUNK; ++ch) {
        const int cur = ch & 1;
        const uint32_t bufb = sb + (uint32_t)(cur * BUF_BYTES);
        const uint32_t nbufb = sb + (uint32_t)((cur ^ 1) * BUF_BYTES);
        const int nxt = (cur ^ 1) * BUF_BYTES;
        const bool sv = (ch + 1 < NCHUNK);
        const int cb  = (ch + 1) * 8;     // channel base of next chunk

        float vH[3][4];

        if (sv) { W_CP(nbufb, ch + 1, 0, 3); GATHER_HALF(vH, cb, 0); }
        MMA_PART(bufb, 0, 2);
        if (sv) COMMIT_HALF(vH, nxt, 0);

        if (sv) { W_CP(nbufb, ch + 1, 3, 6); GATHER_HALF(vH, cb, 4); }
        MMA_PART(bufb, 2, 5);
        if (sv) COMMIT_HALF(vH, nxt, 4);

        CP_WAIT0();
        __syncthreads();
    }

    // ---- epilogue: + bias, float2 stores ------------------------------------
#pragma unroll
    for (int mi = 0; mi < 2; ++mi) {
#pragma unroll
        for (int half = 0; half < 2; ++half) {
            const int o = wm * 32 + mi * 16 + grp + half * 8;
            const float bi = __ldg(bias + o);
            float* po = out + (((size_t)bIdx * 128 + o) << 12) + (h0 << 6);
#pragma unroll
            for (int ni = 0; ni < 4; ++ni) {
                const int n = wn * 32 + ni * 8 + qp * 2;
                float2 v;
                v.x = acc[mi][ni][half * 2 + 0] + bi;
                v.y = acc[mi][ni][half * 2 + 1] + bi;
                *(float2*)(po + n) = v;
            }
        }
    }
}

extern "C" void kernel_launch(void* const* d_in, const int* in_sizes, int n_in,
                              void* d_out, int out_size) {
    const float* x       = (const float*)d_in[0];
    const float* offsets = (const float*)d_in[1];
    const float* mask    = (const float*)d_in[2];
    const float* weight  = (const float*)d_in[3];
    const float* bias    = (const float*)d_in[4];
    float* out = (float*)d_out;

    cudaFuncSetAttribute(dcn_v2_kernel,
                         cudaFuncAttributeMaxDynamicSharedMemorySize, SMEM_BYTES);

    wprep_kernel<<<16, 512>>>(weight);
    dcn_v2_kernel<<<256, NTHREADS, SMEM_BYTES>>>(x, offsets, mask, bias, out);
}

// round 16
// speedup vs baseline: 1.7339x; 1.0541x over previous
#include <cuda_runtime.h>
#include <cuda_bf16.h>
#include <cstdint>

// DCNv2 R16: R15 (cp.async W images + fused gather + hi/lo mma.sync GEMM)
// with the k-pad removed: 72-k chunks run 4 x m16n8k16 steps + 1 x m16n8k8
// tail. No zero padding anywhere; S tile 72x256B, W rows 144B.
// CTA: M=128 outputs x N=128 pixels, grid=256, 512 threads, 4x4 warps m32n32.
// 3 MMA passes (hi*hi, hi*lo, lo*hi) accumulate fp32 -> ~fp32 accuracy.

#define NTHREADS 512
#define NCHUNK 16
#define LDT 72                       // W tile row length (bf16), 144B rows

#define T_WHI 0                      // W hi: 128 x 144B = 18432
#define T_WLO 18432
#define T_SHI 36864                  // S hi: 72 x 256B = 18432
#define T_SLO 55296
#define BUF_BYTES 73728
#define SMEM_BYTES (2 * BUF_BYTES)   // 147456

#define W_IMG_BYTES 36864            // hi tile + lo tile
#define W_CP_CHUNKS (W_IMG_BYTES / 16)   // 2304

__device__ __align__(16) char g_wsp[16 * W_IMG_BYTES];

#define MMA_BF16(d, a, b)                                                     \
    asm volatile(                                                             \
        "mma.sync.aligned.m16n8k16.row.col.f32.bf16.bf16.f32 "                \
        "{%0,%1,%2,%3}, {%4,%5,%6,%7}, {%8,%9}, {%0,%1,%2,%3};"               \
        : "+f"((d)[0]), "+f"((d)[1]), "+f"((d)[2]), "+f"((d)[3])              \
        : "r"((a)[0]), "r"((a)[1]), "r"((a)[2]), "r"((a)[3]),                 \
          "r"((b)[0]), "r"((b)[1]))

#define MMA_BF16_K8(d, a, b)                                                  \
    asm volatile(                                                             \
        "mma.sync.aligned.m16n8k8.row.col.f32.bf16.bf16.f32 "                 \
        "{%0,%1,%2,%3}, {%4,%5}, {%6}, {%0,%1,%2,%3};"                        \
        : "+f"((d)[0]), "+f"((d)[1]), "+f"((d)[2]), "+f"((d)[3])              \
        : "r"((a)[0]), "r"((a)[1]), "r"(b))

#define LDSM_X4(r, addr)                                                      \
    asm volatile("ldmatrix.sync.aligned.m8n8.x4.shared.b16 {%0,%1,%2,%3}, [%4];" \
                 : "=r"((r)[0]), "=r"((r)[1]), "=r"((r)[2]), "=r"((r)[3])     \
                 : "r"(addr))

#define LDSM_X4T(r, addr)                                                     \
    asm volatile("ldmatrix.sync.aligned.m8n8.x4.trans.shared.b16 {%0,%1,%2,%3}, [%4];" \
                 : "=r"((r)[0]), "=r"((r)[1]), "=r"((r)[2]), "=r"((r)[3])     \
                 : "r"(addr))

#define CP16(DST, SRC)                                                        \
    asm volatile("cp.async.cg.shared.global [%0], [%1], 16;"                  \
                 :: "r"(DST), "l"(SRC) : "memory")
#define CP_COMMIT() asm volatile("cp.async.commit_group;" ::: "memory")
#define CP_WAIT0()  asm volatile("cp.async.wait_group 0;" ::: "memory")

__device__ __forceinline__ uint32_t smem_u32(const void* p) {
    uint32_t a;
    asm("{ .reg .u64 t; cvta.to.shared.u64 t, %1; cvt.u32.u64 %0, t; }" : "=r"(a) : "l"(p));
    return a;
}

// ---- prep: split W into bf16 hi/lo tile images (144B rows, no pad) --------
__global__ void __launch_bounds__(512)
wprep_kernel(const float* __restrict__ weight) {
    const int ch = blockIdx.x;
    char* base = g_wsp + (size_t)ch * W_IMG_BYTES;
    for (int i = threadIdx.x; i < 2304; i += 512) {
        const int o = i / 18, kq = i - o * 18;
        const float4 f = *(const float4*)(weight + (size_t)o * 1152 + ch * 72 + kq * 4);
        __nv_bfloat162 h01 = __floats2bfloat162_rn(f.x, f.y);
        __nv_bfloat162 h23 = __floats2bfloat162_rn(f.z, f.w);
        const float2 g01 = __bfloat1622float2(h01);
        const float2 g23 = __bfloat1622float2(h23);
        __nv_bfloat162 l01 = __floats2bfloat162_rn(f.x - g01.x, f.y - g01.y);
        __nv_bfloat162 l23 = __floats2bfloat162_rn(f.z - g23.x, f.w - g23.y);
        const int bo = o * 144 + kq * 8;
        *(uint2*)(base + bo)         = make_uint2(*(uint32_t*)&h01, *(uint32_t*)&h23);
        *(uint2*)(base + 18432 + bo) = make_uint2(*(uint32_t*)&l01, *(uint32_t*)&l23);
    }
}

__global__ void __launch_bounds__(NTHREADS, 1)
dcn_v2_kernel(const float* __restrict__ x,
              const float* __restrict__ offsets,
              const float* __restrict__ mask,
              const float* __restrict__ bias,
              float* __restrict__ out) {
    extern __shared__ char smem[];
    const uint32_t sb = smem_u32(smem);

    const int tid  = threadIdx.x;
    const int wid  = tid >> 5;
    const int lane = tid & 31;
    const int grp  = lane >> 2;
    const int qp   = lane & 3;
    const int wm   = wid >> 2;
    const int wn   = wid & 3;

    const int bIdx = blockIdx.x >> 5;
    const int h0   = (blockIdx.x & 31) << 1;
    const float* xp = x + ((size_t)bIdx << 19);

    // ---- register-resident bilinear taps ----------------------------------
    const int ntaps = 2 + (tid < 128);
    uint2  tio[3];
    float4 twt[3];
#pragma unroll
    for (int j = 0; j < 3; ++j) {
        tio[j] = make_uint2(0u, 0u);
        twt[j] = make_float4(0.f, 0.f, 0.f, 0.f);
        if (j < ntaps) {
            const int e   = tid + (j << 9);
            const int t   = e >> 7;
            const int pix = e & 127;
            const int h   = h0 + (pix >> 6);
            const int wp  = pix & 63;
            const int ky  = t / 3;
            const int kx  = t - ky * 3;
            const int hw  = (h << 6) + wp;

            const size_t ob = ((size_t)bIdx * 18) << 12;
            const float dy = offsets[ob + ((size_t)(2 * t) << 12) + hw];
            const float dx = offsets[ob + ((size_t)(2 * t + 1) << 12) + hw];
            const float m  = mask[(((size_t)bIdx * 9 + t) << 12) + hw];

            const float py = (float)(h - 1 + ky) + dy;
            const float px = (float)(wp - 1 + kx) + dx;
            const float fy = floorf(py), fx = floorf(px);
            const float ay = py - fy, ax = px - fx;
            const float by = 1.f - ay, bx = 1.f - ax;
            const float fy1 = fy + 1.f, fx1 = fx + 1.f;
            const bool vy0 = (fy  >= 0.f) && (fy  <= 63.f);
            const bool vy1 = (fy1 >= 0.f) && (fy1 <= 63.f);
            const bool vx0 = (fx  >= 0.f) && (fx  <= 63.f);
            const bool vx1 = (fx1 >= 0.f) && (fx1 <= 63.f);
            const int y0 = (int)fminf(fmaxf(fy,  0.f), 63.f);
            const int y1 = (int)fminf(fmaxf(fy1, 0.f), 63.f);
            const int x0 = (int)fminf(fmaxf(fx,  0.f), 63.f);
            const int x1 = (int)fminf(fmaxf(fx1, 0.f), 63.f);
            const unsigned i0 = (unsigned)((y0 << 6) + x0);
            const unsigned i1 = (unsigned)((y0 << 6) + x1);
            const unsigned i2 = (unsigned)((y1 << 6) + x0);
            const unsigned i3 = (unsigned)((y1 << 6) + x1);
            tio[j] = make_uint2(i0 | (i1 << 16), i2 | (i3 << 16));
            twt[j] = make_float4((vy0 && vx0) ? by * bx * m : 0.f,
                                 (vy0 && vx1) ? by * ax * m : 0.f,
                                 (vy1 && vx0) ? ay * bx * m : 0.f,
                                 (vy1 && vx1) ? ay * ax * m : 0.f);
        }
    }

    float acc[2][4][4];
#pragma unroll
    for (int mi = 0; mi < 2; ++mi)
#pragma unroll
        for (int ni = 0; ni < 4; ++ni)
#pragma unroll
            for (int q = 0; q < 4; ++q) acc[mi][ni][q] = 0.f;

    // ---- staging helpers ---------------------------------------------------
#define GATHER_HALF(V, CB, U0)                                                \
    do {                                                                      \
        const float* qc = xp + ((size_t)(CB) << 12);                          \
        _Pragma("unroll")                                                     \
        for (int j = 0; j < 3; ++j) {                                         \
            if (j < ntaps) {                                                  \
                const float4 w = twt[j];                                      \
                const float* b0 = qc + (tio[j].x & 0xFFFF);                   \
                const float* b1 = qc + (tio[j].x >> 16);                      \
                const float* b2 = qc + (tio[j].y & 0xFFFF);                   \
                const float* b3 = qc + (tio[j].y >> 16);                      \
                _Pragma("unroll")                                             \
                for (int u = 0; u < 4; ++u) {                                 \
                    const int co = ((U0) + u) << 12;                          \
                    V[j][u] = fmaf(w.x, __ldg(b0 + co),                       \
                              fmaf(w.y, __ldg(b1 + co),                       \
                              fmaf(w.z, __ldg(b2 + co),                       \
                                   w.w * __ldg(b3 + co))));                   \
                }                                                             \
            }                                                                 \
        }                                                                     \
    } while (0)

#define COMMIT_HALF(V, BUFB_HOST, U0)                                         \
    do {                                                                      \
        char* shi = smem + (BUFB_HOST) + T_SHI;                               \
        char* slo = smem + (BUFB_HOST) + T_SLO;                               \
        _Pragma("unroll")                                                     \
        for (int j = 0; j < 3; ++j) {                                         \
            if (j < ntaps) {                                                  \
                const int e    = tid + (j << 9);                              \
                const int t    = e >> 7;                                      \
                const int pix2 = (e & 127) * 2;                               \
                const int tb   = t << 8;                                      \
                const int t4   = t << 4;                                      \
                _Pragma("unroll")                                             \
                for (int u = 0; u < 4; ++u) {                                 \
                    const int c = (U0) + u;                                   \
                    const float v = V[j][u];                                  \
                    const __nv_bfloat16 hb = __float2bfloat16(v);             \
                    const __nv_bfloat16 lb =                                  \
                        __float2bfloat16(v - __bfloat162float(hb));           \
                    const int ad = tb + c * 2304 +                            \
                                   (pix2 ^ ((t4 + (c << 4)) & 0x70));         \
                    *(__nv_bfloat16*)(shi + ad) = hb;                         \
                    *(__nv_bfloat16*)(slo + ad) = lb;                         \
                }                                                             \
            }                                                                 \
        }                                                                     \
    } while (0)

    // W stage: async flat copy of the pre-built tile image (2304 x 16B)
#define W_CP(BUFB_U32, CH, IT0, IT1)                                          \
    do {                                                                      \
        const char* wsrc = g_wsp + (size_t)(CH) * W_IMG_BYTES;                \
        _Pragma("unroll")                                                     \
        for (int it = (IT0); it < (IT1); ++it) {                              \
            const int idx = tid + it * NTHREADS;                              \
            if (idx < W_CP_CHUNKS)                                            \
                CP16((BUFB_U32) + (uint32_t)(idx * 16), wsrc + idx * 16);     \
        }                                                                     \
        CP_COMMIT();                                                          \
    } while (0)

    // ---- MMA lane addressing -----------------------------------------------
    const int lr   = lane >> 3;
    const int lrow = lane & 7;
    const uint32_t a_lane_off =
        (uint32_t)(((wm * 32 + (lr & 1) * 8 + lrow) * LDT + (lr >> 1) * 8) * 2);
    const uint32_t b_lane_const =
        (uint32_t)(((lr & 1) * 8 + lrow) * 256) + (uint32_t)((lr >> 1) ? T_SLO : T_SHI);
    const uint32_t xorv = (uint32_t)(lrow << 4);
    const uint32_t wn64 = (uint32_t)(wn * 64);

    // tail (k64..71) addressing
    const uint32_t a_tail_off = (uint32_t)((wm * 32 + lane) * 144 + 128);
    const uint32_t b_tail_const =
        (uint32_t)((64 + lrow) * 256) + (uint32_t)((lr >> 1) ? T_SLO : T_SHI);
    const uint32_t b_tail_n = wn64 + (uint32_t)((lr & 1) * 16);

#define MMA_PART(BUFB, KS0, KS1)                                              \
    do {                                                                      \
        const uint32_t whiA = (BUFB) + T_WHI + a_lane_off;                    \
        const uint32_t wloA = (BUFB) + T_WLO + a_lane_off;                    \
        const uint32_t bB   = (BUFB) + b_lane_const;                          \
        _Pragma("unroll")                                                     \
        for (int ks = (KS0); ks < (KS1); ++ks) {                              \
            uint32_t ahi[2][4], alo[2][4];                                    \
            _Pragma("unroll")                                                 \
            for (int mi = 0; mi < 2; ++mi) {                                  \
                LDSM_X4(ahi[mi], whiA + (uint32_t)((mi * 16 * LDT + ks * 16) * 2)); \
                LDSM_X4(alo[mi], wloA + (uint32_t)((mi * 16 * LDT + ks * 16) * 2)); \
            }                                                                 \
            _Pragma("unroll")                                                 \
            for (int ni = 0; ni < 4; ++ni) {                                  \
                uint32_t b4[4];                                               \
                LDSM_X4T(b4, bB + (uint32_t)(ks * 4096) +                     \
                              ((wn64 + (uint32_t)(ni * 16)) ^ xorv));         \
                _Pragma("unroll")                                             \
                for (int mi = 0; mi < 2; ++mi) {                              \
                    MMA_BF16(acc[mi][ni], ahi[mi], b4);                       \
                    MMA_BF16(acc[mi][ni], ahi[mi], b4 + 2);                   \
                    MMA_BF16(acc[mi][ni], alo[mi], b4);                       \
                }                                                             \
            }                                                                 \
        }                                                                     \
    } while (0)

    // k8 tail: A m32@k64 (one x4 per tile), B hi/lo x n32 (two x4T)
#define MMA_TAIL(BUFB)                                                        \
    do {                                                                      \
        uint32_t ath[4], atl[4];                                              \
        LDSM_X4(ath, (BUFB) + T_WHI + a_tail_off);                            \
        LDSM_X4(atl, (BUFB) + T_WLO + a_tail_off);                            \
        uint32_t bt0[4], bt1[4];                                              \
        LDSM_X4T(bt0, (BUFB) + b_tail_const + (b_tail_n ^ xorv));             \
        LDSM_X4T(bt1, (BUFB) + b_tail_const + ((b_tail_n + 32u) ^ xorv));     \
        _Pragma("unroll")                                                     \
        for (int ni = 0; ni < 4; ++ni) {                                      \
            const uint32_t bh = (ni < 2) ? bt0[ni & 1] : bt1[ni & 1];         \
            const uint32_t bl = (ni < 2) ? bt0[2 + (ni & 1)] : bt1[2 + (ni & 1)]; \
            _Pragma("unroll")                                                 \
            for (int mi = 0; mi < 2; ++mi) {                                  \
                MMA_BF16_K8(acc[mi][ni], ath + mi * 2, bh);                   \
                MMA_BF16_K8(acc[mi][ni], ath + mi * 2, bl);                   \
                MMA_BF16_K8(acc[mi][ni], atl + mi * 2, bh);                   \
            }                                                                 \
        }                                                                     \
    } while (0)

    // ---- prologue: fill buffer 0 -------------------------------------------
    {
        W_CP(sb, 0, 0, 5);
        float vA[3][4], vB[3][4];
        GATHER_HALF(vA, 0, 0);
        GATHER_HALF(vB, 0, 4);
        COMMIT_HALF(vA, 0, 0);
        COMMIT_HALF(vB, 0, 4);
        CP_WAIT0();
    }
    __syncthreads();

    // ---- main loop -----------------------------------------------------------
    for (int ch = 0; ch < NCHUNK; ++ch) {
        const int cur = ch & 1;
        const uint32_t bufb = sb + (uint32_t)(cur * BUF_BYTES);
        const uint32_t nbufb = sb + (uint32_t)((cur ^ 1) * BUF_BYTES);
        const int nxt = (cur ^ 1) * BUF_BYTES;
        const bool sv = (ch + 1 < NCHUNK);
        const int cb  = (ch + 1) * 8;

        float vH[3][4];

        if (sv) { W_CP(nbufb, ch + 1, 0, 3); GATHER_HALF(vH, cb, 0); }
        MMA_PART(bufb, 0, 2);
        if (sv) COMMIT_HALF(vH, nxt, 0);

        if (sv) { W_CP(nbufb, ch + 1, 3, 5); GATHER_HALF(vH, cb, 4); }
        MMA_PART(bufb, 2, 4);
        MMA_TAIL(bufb);
        if (sv) COMMIT_HALF(vH, nxt, 4);

        CP_WAIT0();
        __syncthreads();
    }

    // ---- epilogue: + bias, float2 stores ------------------------------------
#pragma unroll
    for (int mi = 0; mi < 2; ++mi) {
#pragma unroll
        for (int half = 0; half < 2; ++half) {
            const int o = wm * 32 + mi * 16 + grp + half * 8;
            const float bi = __ldg(bias + o);
            float* po = out + (((size_t)bIdx * 128 + o) << 12) + (h0 << 6);
#pragma unroll
            for (int ni = 0; ni < 4; ++ni) {
                const int n = wn * 32 + ni * 8 + qp * 2;
                float2 v;
                v.x = acc[mi][ni][half * 2 + 0] + bi;
                v.y = acc[mi][ni][half * 2 + 1] + bi;
                *(float2*)(po + n) = v;
            }
        }
    }
}

extern "C" void kernel_launch(void* const* d_in, const int* in_sizes, int n_in,
                              void* d_out, int out_size) {
    const float* x       = (const float*)d_in[0];
    const float* offsets = (const float*)d_in[1];
    const float* mask    = (const float*)d_in[2];
    const float* weight  = (const float*)d_in[3];
    const float* bias    = (const float*)d_in[4];
    float* out = (float*)d_out;

    cudaFuncSetAttribute(dcn_v2_kernel,
                         cudaFuncAttributeMaxDynamicSharedMemorySize, SMEM_BYTES);

    wprep_kernel<<<16, 512>>>(weight);
    dcn_v2_kernel<<<256, NTHREADS, SMEM_BYTES>>>(x, offsets, mask, bias, out);
}

// round 17
// speedup vs baseline: 2.0080x; 1.1581x over previous
#include <cuda_runtime.h>
#include <cuda_fp16.h>
#include <cstdint>

// DCNv2 R17: fp16 hi/lo split, 2 MMA passes (Wh*Sh + Wh*Sl). W is hi-only.
// Error budget: dropped Wl*S term ~2^-11/sqrt(3) ~ 2-3e-4 rel (bound 1e-3).
// Structure = R16: cp.async W images, fused gather, 72-k chunks, k16x4 + k8
// tail, swizzled k-major S tile, 4x4 warp grid m32n32, grid=256, 512 thr.

#define NTHREADS 512
#define NCHUNK 16
#define LDT 72                       // W tile row length (fp16), 144B rows

#define T_WHI 0                      // W hi: 128 x 144B = 18432
#define T_SHI 18432                  // S hi: 72 x 256B = 18432
#define T_SLO 36864
#define BUF_BYTES 55296
#define SMEM_BYTES (2 * BUF_BYTES)   // 110592

#define W_IMG_BYTES 18432            // hi tile only
#define W_CP_CHUNKS (W_IMG_BYTES / 16)   // 1152

__device__ __align__(16) char g_wsp[16 * W_IMG_BYTES];

#define MMA_F16(d, a, b)                                                      \
    asm volatile(                                                             \
        "mma.sync.aligned.m16n8k16.row.col.f32.f16.f16.f32 "                  \
        "{%0,%1,%2,%3}, {%4,%5,%6,%7}, {%8,%9}, {%0,%1,%2,%3};"               \
        : "+f"((d)[0]), "+f"((d)[1]), "+f"((d)[2]), "+f"((d)[3])              \
        : "r"((a)[0]), "r"((a)[1]), "r"((a)[2]), "r"((a)[3]),                 \
          "r"((b)[0]), "r"((b)[1]))

#define MMA_F16_K8(d, a, b)                                                   \
    asm volatile(                                                             \
        "mma.sync.aligned.m16n8k8.row.col.f32.f16.f16.f32 "                   \
        "{%0,%1,%2,%3}, {%4,%5}, {%6}, {%0,%1,%2,%3};"                        \
        : "+f"((d)[0]), "+f"((d)[1]), "+f"((d)[2]), "+f"((d)[3])              \
        : "r"((a)[0]), "r"((a)[1]), "r"(b))

#define LDSM_X4(r, addr)                                                      \
    asm volatile("ldmatrix.sync.aligned.m8n8.x4.shared.b16 {%0,%1,%2,%3}, [%4];" \
                 : "=r"((r)[0]), "=r"((r)[1]), "=r"((r)[2]), "=r"((r)[3])     \
                 : "r"(addr))

#define LDSM_X4T(r, addr)                                                     \
    asm volatile("ldmatrix.sync.aligned.m8n8.x4.trans.shared.b16 {%0,%1,%2,%3}, [%4];" \
                 : "=r"((r)[0]), "=r"((r)[1]), "=r"((r)[2]), "=r"((r)[3])     \
                 : "r"(addr))

#define CP16(DST, SRC)                                                        \
    asm volatile("cp.async.cg.shared.global [%0], [%1], 16;"                  \
                 :: "r"(DST), "l"(SRC) : "memory")
#define CP_COMMIT() asm volatile("cp.async.commit_group;" ::: "memory")
#define CP_WAIT0()  asm volatile("cp.async.wait_group 0;" ::: "memory")

__device__ __forceinline__ uint32_t smem_u32(const void* p) {
    uint32_t a;
    asm("{ .reg .u64 t; cvta.to.shared.u64 t, %1; cvt.u32.u64 %0, t; }" : "=r"(a) : "l"(p));
    return a;
}

// ---- prep: W -> fp16 hi tile images (144B rows) ---------------------------
__global__ void __launch_bounds__(512)
wprep_kernel(const float* __restrict__ weight) {
    const int ch = blockIdx.x;
    char* base = g_wsp + (size_t)ch * W_IMG_BYTES;
    for (int i = threadIdx.x; i < 2304; i += 512) {
        const int o = i / 18, kq = i - o * 18;
        const float4 f = *(const float4*)(weight + (size_t)o * 1152 + ch * 72 + kq * 4);
        __half2 h01 = __floats2half2_rn(f.x, f.y);
        __half2 h23 = __floats2half2_rn(f.z, f.w);
        *(uint2*)(base + o * 144 + kq * 8) =
            make_uint2(*(uint32_t*)&h01, *(uint32_t*)&h23);
    }
}

__global__ void __launch_bounds__(NTHREADS, 1)
dcn_v2_kernel(const float* __restrict__ x,
              const float* __restrict__ offsets,
              const float* __restrict__ mask,
              const float* __restrict__ bias,
              float* __restrict__ out) {
    extern __shared__ char smem[];
    const uint32_t sb = smem_u32(smem);

    const int tid  = threadIdx.x;
    const int wid  = tid >> 5;
    const int lane = tid & 31;
    const int grp  = lane >> 2;
    const int qp   = lane & 3;
    const int wm   = wid >> 2;
    const int wn   = wid & 3;

    const int bIdx = blockIdx.x >> 5;
    const int h0   = (blockIdx.x & 31) << 1;
    const float* xp = x + ((size_t)bIdx << 19);

    // ---- register-resident bilinear taps ----------------------------------
    const int ntaps = 2 + (tid < 128);
    uint2  tio[3];
    float4 twt[3];
#pragma unroll
    for (int j = 0; j < 3; ++j) {
        tio[j] = make_uint2(0u, 0u);
        twt[j] = make_float4(0.f, 0.f, 0.f, 0.f);
        if (j < ntaps) {
            const int e   = tid + (j << 9);
            const int t   = e >> 7;
            const int pix = e & 127;
            const int h   = h0 + (pix >> 6);
            const int wp  = pix & 63;
            const int ky  = t / 3;
            const int kx  = t - ky * 3;
            const int hw  = (h << 6) + wp;

            const size_t ob = ((size_t)bIdx * 18) << 12;
            const float dy = offsets[ob + ((size_t)(2 * t) << 12) + hw];
            const float dx = offsets[ob + ((size_t)(2 * t + 1) << 12) + hw];
            const float m  = mask[(((size_t)bIdx * 9 + t) << 12) + hw];

            const float py = (float)(h - 1 + ky) + dy;
            const float px = (float)(wp - 1 + kx) + dx;
            const float fy = floorf(py), fx = floorf(px);
            const float ay = py - fy, ax = px - fx;
            const float by = 1.f - ay, bx = 1.f - ax;
            const float fy1 = fy + 1.f, fx1 = fx + 1.f;
            const bool vy0 = (fy  >= 0.f) && (fy  <= 63.f);
            const bool vy1 = (fy1 >= 0.f) && (fy1 <= 63.f);
            const bool vx0 = (fx  >= 0.f) && (fx  <= 63.f);
            const bool vx1 = (fx1 >= 0.f) && (fx1 <= 63.f);
            const int y0 = (int)fminf(fmaxf(fy,  0.f), 63.f);
            const int y1 = (int)fminf(fmaxf(fy1, 0.f), 63.f);
            const int x0 = (int)fminf(fmaxf(fx,  0.f), 63.f);
            const int x1 = (int)fminf(fmaxf(fx1, 0.f), 63.f);
            const unsigned i0 = (unsigned)((y0 << 6) + x0);
            const unsigned i1 = (unsigned)((y0 << 6) + x1);
            const unsigned i2 = (unsigned)((y1 << 6) + x0);
            const unsigned i3 = (unsigned)((y1 << 6) + x1);
            tio[j] = make_uint2(i0 | (i1 << 16), i2 | (i3 << 16));
            twt[j] = make_float4((vy0 && vx0) ? by * bx * m : 0.f,
                                 (vy0 && vx1) ? by * ax * m : 0.f,
                                 (vy1 && vx0) ? ay * bx * m : 0.f,
                                 (vy1 && vx1) ? ay * ax * m : 0.f);
        }
    }

    float acc[2][4][4];
#pragma unroll
    for (int mi = 0; mi < 2; ++mi)
#pragma unroll
        for (int ni = 0; ni < 4; ++ni)
#pragma unroll
            for (int q = 0; q < 4; ++q) acc[mi][ni][q] = 0.f;

    // ---- staging helpers ---------------------------------------------------
#define GATHER_HALF(V, CB, U0)                                                \
    do {                                                                      \
        const float* qc = xp + ((size_t)(CB) << 12);                          \
        _Pragma("unroll")                                                     \
        for (int j = 0; j < 3; ++j) {                                         \
            if (j < ntaps) {                                                  \
                const float4 w = twt[j];                                      \
                const float* b0 = qc + (tio[j].x & 0xFFFF);                   \
                const float* b1 = qc + (tio[j].x >> 16);                      \
                const float* b2 = qc + (tio[j].y & 0xFFFF);                   \
                const float* b3 = qc + (tio[j].y >> 16);                      \
                _Pragma("unroll")                                             \
                for (int u = 0; u < 4; ++u) {                                 \
                    const int co = ((U0) + u) << 12;                          \
                    V[j][u] = fmaf(w.x, __ldg(b0 + co),                       \
                              fmaf(w.y, __ldg(b1 + co),                       \
                              fmaf(w.z, __ldg(b2 + co),                       \
                                   w.w * __ldg(b3 + co))));                   \
                }                                                             \
            }                                                                 \
        }                                                                     \
    } while (0)

#define COMMIT_HALF(V, BUFB_HOST, U0)                                         \
    do {                                                                      \
        char* shi = smem + (BUFB_HOST) + T_SHI;                               \
        char* slo = smem + (BUFB_HOST) + T_SLO;                               \
        _Pragma("unroll")                                                     \
        for (int j = 0; j < 3; ++j) {                                         \
            if (j < ntaps) {                                                  \
                const int e    = tid + (j << 9);                              \
                const int t    = e >> 7;                                      \
                const int pix2 = (e & 127) * 2;                               \
                const int tb   = t << 8;                                      \
                const int t4   = t << 4;                                      \
                _Pragma("unroll")                                             \
                for (int u = 0; u < 4; ++u) {                                 \
                    const int c = (U0) + u;                                   \
                    const float v = V[j][u];                                  \
                    const __half hb = __float2half_rn(v);                     \
                    const __half lb = __float2half_rn(v - __half2float(hb));  \
                    const int ad = tb + c * 2304 +                            \
                                   (pix2 ^ ((t4 + (c << 4)) & 0x70));         \
                    *(__half*)(shi + ad) = hb;                                \
                    *(__half*)(slo + ad) = lb;                                \
                }                                                             \
            }                                                                 \
        }                                                                     \
    } while (0)

    // W stage: async flat copy (1152 x 16B)
#define W_CP(BUFB_U32, CH, IT0, IT1)                                          \
    do {                                                                      \
        const char* wsrc = g_wsp + (size_t)(CH) * W_IMG_BYTES;                \
        _Pragma("unroll")                                                     \
        for (int it = (IT0); it < (IT1); ++it) {                              \
            const int idx = tid + it * NTHREADS;                              \
            if (idx < W_CP_CHUNKS)                                            \
                CP16((BUFB_U32) + (uint32_t)(idx * 16), wsrc + idx * 16);     \
        }                                                                     \
        CP_COMMIT();                                                          \
    } while (0)

    // ---- MMA lane addressing -----------------------------------------------
    const int lr   = lane >> 3;
    const int lrow = lane & 7;
    const uint32_t a_lane_off =
        (uint32_t)(((wm * 32 + (lr & 1) * 8 + lrow) * LDT + (lr >> 1) * 8) * 2);
    const uint32_t b_lane_const =
        (uint32_t)(((lr & 1) * 8 + lrow) * 256) + (uint32_t)((lr >> 1) ? T_SLO : T_SHI);
    const uint32_t xorv = (uint32_t)(lrow << 4);
    const uint32_t wn64 = (uint32_t)(wn * 64);

    // tail (k64..71) addressing
    const uint32_t a_tail_off = (uint32_t)((wm * 32 + lane) * 144 + 128);
    const uint32_t b_tail_const =
        (uint32_t)((64 + lrow) * 256) + (uint32_t)((lr >> 1) ? T_SLO : T_SHI);
    const uint32_t b_tail_n = wn64 + (uint32_t)((lr & 1) * 16);

#define MMA_PART(BUFB, KS0, KS1)                                              \
    do {                                                                      \
        const uint32_t whiA = (BUFB) + T_WHI + a_lane_off;                    \
        const uint32_t bB   = (BUFB) + b_lane_const;                          \
        _Pragma("unroll")                                                     \
        for (int ks = (KS0); ks < (KS1); ++ks) {                              \
            uint32_t ahi[2][4];                                               \
            _Pragma("unroll")                                                 \
            for (int mi = 0; mi < 2; ++mi)                                    \
                LDSM_X4(ahi[mi], whiA + (uint32_t)((mi * 16 * LDT + ks * 16) * 2)); \
            _Pragma("unroll")                                                 \
            for (int ni = 0; ni < 4; ++ni) {                                  \
                uint32_t b4[4];   /* {hi k0, hi k8, lo k0, lo k8} */          \
                LDSM_X4T(b4, bB + (uint32_t)(ks * 4096) +                     \
                              ((wn64 + (uint32_t)(ni * 16)) ^ xorv));         \
                _Pragma("unroll")                                             \
                for (int mi = 0; mi < 2; ++mi) {                              \
                    MMA_F16(acc[mi][ni], ahi[mi], b4);                        \
                    MMA_F16(acc[mi][ni], ahi[mi], b4 + 2);                    \
                }                                                             \
            }                                                                 \
        }                                                                     \
    } while (0)

#define MMA_TAIL(BUFB)                                                        \
    do {                                                                      \
        uint32_t ath[4];                                                      \
        LDSM_X4(ath, (BUFB) + T_WHI + a_tail_off);                            \
        uint32_t bt0[4], bt1[4];                                              \
        LDSM_X4T(bt0, (BUFB) + b_tail_const + (b_tail_n ^ xorv));             \
        LDSM_X4T(bt1, (BUFB) + b_tail_const + ((b_tail_n + 32u) ^ xorv));     \
        _Pragma("unroll")                                                     \
        for (int ni = 0; ni < 4; ++ni) {                                      \
            const uint32_t bh = (ni < 2) ? bt0[ni & 1] : bt1[ni & 1];         \
            const uint32_t bl = (ni < 2) ? bt0[2 + (ni & 1)] : bt1[2 + (ni & 1)]; \
            _Pragma("unroll")                                                 \
            for (int mi = 0; mi < 2; ++mi) {                                  \
                MMA_F16_K8(acc[mi][ni], ath + mi * 2, bh);                    \
                MMA_F16_K8(acc[mi][ni], ath + mi * 2, bl);                    \
            }                                                                 \
        }                                                                     \
    } while (0)

    // ---- prologue: fill buffer 0 -------------------------------------------
    {
        W_CP(sb, 0, 0, 3);
        float vA[3][4], vB[3][4];
        GATHER_HALF(vA, 0, 0);
        GATHER_HALF(vB, 0, 4);
        COMMIT_HALF(vA, 0, 0);
        COMMIT_HALF(vB, 0, 4);
        CP_WAIT0();
    }
    __syncthreads();

    // ---- main loop -----------------------------------------------------------
    for (int ch = 0; ch < NCHUNK; ++ch) {
        const int cur = ch & 1;
        const uint32_t bufb = sb + (uint32_t)(cur * BUF_BYTES);
        const uint32_t nbufb = sb + (uint32_t)((cur ^ 1) * BUF_BYTES);
        const int nxt = (cur ^ 1) * BUF_BYTES;
        const bool sv = (ch + 1 < NCHUNK);
        const int cb  = (ch + 1) * 8;

        float vH[3][4];

        if (sv) { W_CP(nbufb, ch + 1, 0, 2); GATHER_HALF(vH, cb, 0); }
        MMA_PART(bufb, 0, 2);
        if (sv) COMMIT_HALF(vH, nxt, 0);

        if (sv) { W_CP(nbufb, ch + 1, 2, 3); GATHER_HALF(vH, cb, 4); }
        MMA_PART(bufb, 2, 4);
        MMA_TAIL(bufb);
        if (sv) COMMIT_HALF(vH, nxt, 4);

        CP_WAIT0();
        __syncthreads();
    }

    // ---- epilogue: + bias, float2 stores ------------------------------------
#pragma unroll
    for (int mi = 0; mi < 2; ++mi) {
#pragma unroll
        for (int half = 0; half < 2; ++half) {
            const int o = wm * 32 + mi * 16 + grp + half * 8;
            const float bi = __ldg(bias + o);
            float* po = out + (((size_t)bIdx * 128 + o) << 12) + (h0 << 6);
#pragma unroll
            for (int ni = 0; ni < 4; ++ni) {
                const int n = wn * 32 + ni * 8 + qp * 2;
                float2 v;
                v.x = acc[mi][ni][half * 2 + 0] + bi;
                v.y = acc[mi][ni][half * 2 + 1] + bi;
                *(float2*)(po + n) = v;
            }
        }
    }
}

extern "C" void kernel_launch(void* const* d_in, const int* in_sizes, int n_in,
                              void* d_out, int out_size) {
    const float* x       = (const float*)d_in[0];
    const float* offsets = (const float*)d_in[1];
    const float* mask    = (const float*)d_in[2];
    const float* weight  = (const float*)d_in[3];
    const float* bias    = (const float*)d_in[4];
    float* out = (float*)d_out;

    cudaFuncSetAttribute(dcn_v2_kernel,
                         cudaFuncAttributeMaxDynamicSharedMemorySize, SMEM_BYTES);

    wprep_kernel<<<16, 512>>>(weight);
    dcn_v2_kernel<<<256, NTHREADS, SMEM_BYTES>>>(x, offsets, mask, bias, out);
}